// round 11
// baseline (speedup 1.0000x reference)
#include <cuda_runtime.h>
#include <math.h>

// Inputs (metadata order):
//   d_in[0]: z          float32, n_nodes*512   (n_nodes = 50000)
//   d_in[1]: edge_index int32,   2*n_edges     (n_edges = 150000)
// Output: float32, n_edges

#define D 512
#define ROW_U4 (D / 16)        // 32 uint4 per int8 row (512 bytes)
#define MAX_NODES 50000
#define EPS 1e-6f

// Scratch: quantized normalized rows (25.6 MB) + per-node {scale, sum} pairs.
__device__ uint4  g_q[(size_t)MAX_NODES * ROW_U4];
__device__ float2 g_ss[MAX_NODES];   // x = quant step of normalized row, y = sum of normalized elems

__device__ __forceinline__ unsigned pack4(float x, float y, float z, float w, float k) {
    int q0 = __float2int_rn(x * k);
    int q1 = __float2int_rn(y * k);
    int q2 = __float2int_rn(z * k);
    int q3 = __float2int_rn(w * k);
    q0 = max(-127, min(127, q0));
    q1 = max(-127, min(127, q1));
    q2 = max(-127, min(127, q2));
    q3 = max(-127, min(127, q3));
    return (unsigned)(q0 & 0xFF) | ((unsigned)(q1 & 0xFF) << 8) |
           ((unsigned)(q2 & 0xFF) << 16) | ((unsigned)(q3 & 0xFF) << 24);
}

__device__ __forceinline__ void cp_async16(void* smem_dst, const void* gsrc) {
    unsigned saddr = (unsigned)__cvta_generic_to_shared(smem_dst);
    asm volatile("cp.async.cg.shared.global [%0], [%1], 16;\n" :: "r"(saddr), "l"(gsrc));
}

// ---------------------------------------------------------------------------
// Kernel 1: one warp per node row. Streaming (__ldcs) reads of z so the 102MB
// stream does not evict the freshly written 25.6MB table from L2.
// ---------------------------------------------------------------------------
__global__ void normalize_kernel(const float* __restrict__ z, int n_nodes) {
    int row  = (blockIdx.x * blockDim.x + threadIdx.x) >> 5;
    int lane = threadIdx.x & 31;
    if (row >= n_nodes) return;

    const float4* __restrict__ Z = (const float4*)(z + (size_t)row * D);
    float4 v[4];
    float n2 = 0.f, s = 0.f, mx = 0.f;
#pragma unroll
    for (int j = 0; j < 4; j++) {
        v[j] = __ldcs(Z + lane + 32 * j);   // evict-first
        n2 += v[j].x * v[j].x + v[j].y * v[j].y + v[j].z * v[j].z + v[j].w * v[j].w;
        s  += v[j].x + v[j].y + v[j].z + v[j].w;
        mx = fmaxf(mx, fmaxf(fmaxf(fabsf(v[j].x), fabsf(v[j].y)),
                             fmaxf(fabsf(v[j].z), fabsf(v[j].w))));
    }
#pragma unroll
    for (int off = 16; off > 0; off >>= 1) {
        n2 += __shfl_xor_sync(0xFFFFFFFFu, n2, off);
        s  += __shfl_xor_sync(0xFFFFFFFFu, s,  off);
        mx = fmaxf(mx, __shfl_xor_sync(0xFFFFFFFFu, mx, off));
    }

    float inv = rsqrtf(n2);
    float step = mx * inv * (1.0f / 127.0f);   // quant step of normalized row
    float qk = 127.0f / mx;                    // v_raw * qk == v_norm / step

    if (lane == 0) g_ss[row] = make_float2(step, s * inv);

    uint4 u;
    u.x = pack4(v[0].x, v[0].y, v[0].z, v[0].w, qk);
    u.y = pack4(v[1].x, v[1].y, v[1].z, v[1].w, qk);
    u.z = pack4(v[2].x, v[2].y, v[2].z, v[2].w, qk);
    u.w = pack4(v[3].x, v[3].y, v[3].z, v[3].w, qk);
    g_q[(size_t)row * ROW_U4 + lane] = u;  // coalesced; table stays L2-resident
}

// ---------------------------------------------------------------------------
// Kernel 2: 8 lanes per edge, 4 edges per warp. Rows staged via cp.async
// (MLP 8 with zero register cost -> high occupancy AND high memory
// parallelism), then LDS.128 + dp4a + REDUX.
// SMEM: per warp 4 edges x 2 rows x 512B = 4KB; 8 warps -> 32KB/block.
// ---------------------------------------------------------------------------
__global__ void __launch_bounds__(256)
edge_kernel(const int* __restrict__ ei,
            float* __restrict__ out,
            int n_edges) {
    __shared__ __align__(16) unsigned char sbuf[8 * 4096];

    int gwarp = (blockIdx.x * blockDim.x + threadIdx.x) >> 5;
    int wib   = threadIdx.x >> 5;     // warp in block
    int lane  = threadIdx.x & 31;
    int sub = lane >> 3;              // edge within warp (0..3)
    int sl  = lane & 7;               // lane within edge group (0..7)
    int e = gwarp * 4 + sub;
    if (e >= n_edges) return;

    int ia = __ldg(ei + e);
    int ib = __ldg(ei + n_edges + e);

    // packed scalars: one 8B broadcast load per endpoint
    float2 ssa = g_ss[ia];
    float2 ssb = g_ss[ib];

    const uint4* __restrict__ A = g_q + (size_t)ia * ROW_U4;
    const uint4* __restrict__ B = g_q + (size_t)ib * ROW_U4;

    unsigned char* ebuf = sbuf + wib * 4096 + sub * 1024;   // [A row 512B][B row 512B]
    uint4* sA = (uint4*)ebuf;
    uint4* sB = (uint4*)(ebuf + 512);

    // 8 independent 16B async copies per lane -- no destination registers.
#pragma unroll
    for (int j = 0; j < 4; j++) {
        cp_async16(&sA[sl + 8 * j], &A[sl + 8 * j]);
        cp_async16(&sB[sl + 8 * j], &B[sl + 8 * j]);
    }
    asm volatile("cp.async.commit_group;\n" ::: "memory");
    asm volatile("cp.async.wait_group 0;\n" ::: "memory");
    // Each lane reads back exactly the bytes it copied -> thread-local
    // visibility, no __syncwarp needed.

    int idot = 0;
#pragma unroll
    for (int j = 0; j < 4; j++) {
        uint4 a = sA[sl + 8 * j];
        uint4 b = sB[sl + 8 * j];
        idot = __dp4a((int)a.x, (int)b.x, idot);
        idot = __dp4a((int)a.y, (int)b.y, idot);
        idot = __dp4a((int)a.z, (int)b.z, idot);
        idot = __dp4a((int)a.w, (int)b.w, idot);
    }

    unsigned gmask = 0xFFu << (sub * 8);
    idot = __reduce_add_sync(gmask, idot);

    if (sl == 0) {
        float dot = (float)idot * ssa.x * ssb.x;
        // unit rows: ||a-b+eps||^2 = 2 - 2*dot + 2*eps*(sum_a - sum_b) + D*eps^2
        float d2 = 2.0f - 2.0f * dot
                 + 2.0f * EPS * (ssa.y - ssb.y)
                 + (float)D * EPS * EPS;
        d2 = fmaxf(d2, 0.0f);
        float v = 1.0f - sqrtf(d2);
        out[e] = 1.0f / (1.0f + expf(-v));
    }
}

extern "C" void kernel_launch(void* const* d_in, const int* in_sizes, int n_in,
                              void* d_out, int out_size) {
    const float* z = (const float*)d_in[0];
    const int* ei  = (const int*)d_in[1];
    float* out     = (float*)d_out;

    int n_nodes = in_sizes[0] / D;   // 50000
    int n_edges = out_size;          // 150000

    {
        long long tt = (long long)n_nodes * 32;
        int blocks = (int)((tt + 255) / 256);
        normalize_kernel<<<blocks, 256>>>(z, n_nodes);
    }
    {
        long long warps = ((long long)n_edges + 3) / 4;
        long long tt = warps * 32;
        int blocks = (int)((tt + 255) / 256);
        edge_kernel<<<blocks, 256>>>(ei, out, n_edges);
    }
}

// round 12
// speedup vs baseline: 1.0727x; 1.0727x over previous
#include <cuda_runtime.h>
#include <math.h>

// Inputs (metadata order):
//   d_in[0]: z          float32, n_nodes*512   (n_nodes = 50000)
//   d_in[1]: edge_index int32,   2*n_edges     (n_edges = 150000)
// Output: float32, 150000

#define D 512
#define ROW_U4 (D / 16)        // 32 uint4 per int8 row (512 bytes)
#define MAX_NODES 50000
#define EPS 1e-6f

// Scratch: quantized normalized rows (25.6 MB) + per-node {scale, sum} pairs.
__device__ uint4  g_q[(size_t)MAX_NODES * ROW_U4];
__device__ float2 g_ss[MAX_NODES];   // x = quant step of normalized row, y = sum of normalized elems

__device__ __forceinline__ unsigned pack4(float x, float y, float z, float w, float k) {
    int q0 = __float2int_rn(x * k);
    int q1 = __float2int_rn(y * k);
    int q2 = __float2int_rn(z * k);
    int q3 = __float2int_rn(w * k);
    q0 = max(-127, min(127, q0));
    q1 = max(-127, min(127, q1));
    q2 = max(-127, min(127, q2));
    q3 = max(-127, min(127, q3));
    return (unsigned)(q0 & 0xFF) | ((unsigned)(q1 & 0xFF) << 8) |
           ((unsigned)(q2 & 0xFF) << 16) | ((unsigned)(q3 & 0xFF) << 24);
}

__device__ __forceinline__ void cp_async16(void* smem_dst, const void* gsrc) {
    unsigned saddr = (unsigned)__cvta_generic_to_shared(smem_dst);
    asm volatile("cp.async.cg.shared.global [%0], [%1], 16;\n" :: "r"(saddr), "l"(gsrc));
}

// ---------------------------------------------------------------------------
// Kernel 1: one warp per node row. Streaming (__ldcs) reads of z so the 102MB
// stream does not evict the freshly written 25.6MB table from L2.
// ---------------------------------------------------------------------------
__global__ void normalize_kernel(const float* __restrict__ z, int n_nodes) {
    int row  = (blockIdx.x * blockDim.x + threadIdx.x) >> 5;
    int lane = threadIdx.x & 31;
    if (row >= n_nodes) return;

    const float4* __restrict__ Z = (const float4*)(z + (size_t)row * D);
    float4 v[4];
    float n2 = 0.f, s = 0.f, mx = 0.f;
#pragma unroll
    for (int j = 0; j < 4; j++) {
        v[j] = __ldcs(Z + lane + 32 * j);   // evict-first
        n2 += v[j].x * v[j].x + v[j].y * v[j].y + v[j].z * v[j].z + v[j].w * v[j].w;
        s  += v[j].x + v[j].y + v[j].z + v[j].w;
        mx = fmaxf(mx, fmaxf(fmaxf(fabsf(v[j].x), fabsf(v[j].y)),
                             fmaxf(fabsf(v[j].z), fabsf(v[j].w))));
    }
#pragma unroll
    for (int off = 16; off > 0; off >>= 1) {
        n2 += __shfl_xor_sync(0xFFFFFFFFu, n2, off);
        s  += __shfl_xor_sync(0xFFFFFFFFu, s,  off);
        mx = fmaxf(mx, __shfl_xor_sync(0xFFFFFFFFu, mx, off));
    }

    float inv = rsqrtf(n2);
    float step = mx * inv * (1.0f / 127.0f);   // quant step of normalized row
    float qk = 127.0f / mx;                    // v_raw * qk == v_norm / step

    if (lane == 0) g_ss[row] = make_float2(step, s * inv);

    uint4 u;
    u.x = pack4(v[0].x, v[0].y, v[0].z, v[0].w, qk);
    u.y = pack4(v[1].x, v[1].y, v[1].z, v[1].w, qk);
    u.z = pack4(v[2].x, v[2].y, v[2].z, v[2].w, qk);
    u.w = pack4(v[3].x, v[3].y, v[3].z, v[3].w, qk);
    g_q[(size_t)row * ROW_U4 + lane] = u;  // coalesced; table stays L2-resident
}

// ---------------------------------------------------------------------------
// Kernel 2: persistent warps, 8 lanes/edge, 4 edges per warp-batch,
// double-buffered cp.async pipeline:
//   compute batch i  |  rows of batch i+1 in flight  |  indices of i+2 in flight
// SMEM: 8 warps x 2 stages x 4KB = 64KB/block -> 3 blocks/SM.
// ---------------------------------------------------------------------------
__global__ void __launch_bounds__(256)
edge_kernel(const int* __restrict__ ei,
            float* __restrict__ out,
            int n_edges) {
    __shared__ __align__(16) unsigned char sbuf[8][2][4096];

    int wib  = threadIdx.x >> 5;
    int lane = threadIdx.x & 31;
    int sub  = lane >> 3;      // edge within batch (0..3)
    int sl   = lane & 7;       // lane within 8-lane edge group

    int n_batches = (n_edges + 3) >> 2;
    int warp0   = blockIdx.x * 8 + wib;
    int n_warps = gridDim.x * 8;

    if (warp0 >= n_batches) return;

    // --- prologue -----------------------------------------------------------
    // indices for batch b (current)
    int e0 = warp0 * 4 + sub;
    int e0c = min(e0, n_edges - 1);
    int ia0 = __ldg(ei + e0c);
    int ib0 = __ldg(ei + n_edges + e0c);

    // issue rows for batch b into stage 0
    {
        unsigned char* ebuf = &sbuf[wib][0][sub * 1024];
        const uint4* A = g_q + (size_t)ia0 * ROW_U4;
        const uint4* B = g_q + (size_t)ib0 * ROW_U4;
#pragma unroll
        for (int j = 0; j < 4; j++) {
            cp_async16(ebuf + 16 * (sl + 8 * j),       &A[sl + 8 * j]);
            cp_async16(ebuf + 512 + 16 * (sl + 8 * j), &B[sl + 8 * j]);
        }
        asm volatile("cp.async.commit_group;\n" ::: "memory");
    }
    float2 ssa0 = g_ss[ia0];
    float2 ssb0 = g_ss[ib0];

    // indices for batch b + n_warps
    int ia1 = ia0, ib1 = ib0;
    {
        int bn = warp0 + n_warps;
        if (bn < n_batches) {
            int e1 = bn * 4 + sub;
            int e1c = min(e1, n_edges - 1);
            ia1 = __ldg(ei + e1c);
            ib1 = __ldg(ei + n_edges + e1c);
        }
    }

    int stage = 0;
    for (int b = warp0; b < n_batches; b += n_warps) {
        int  bn        = b + n_warps;
        bool has_next  = (bn < n_batches);
        bool has_next2 = (bn + n_warps < n_batches);

        // issue rows for next batch into the other stage
        if (has_next) {
            unsigned char* ebuf = &sbuf[wib][stage ^ 1][sub * 1024];
            const uint4* A = g_q + (size_t)ia1 * ROW_U4;
            const uint4* B = g_q + (size_t)ib1 * ROW_U4;
#pragma unroll
            for (int j = 0; j < 4; j++) {
                cp_async16(ebuf + 16 * (sl + 8 * j),       &A[sl + 8 * j]);
                cp_async16(ebuf + 512 + 16 * (sl + 8 * j), &B[sl + 8 * j]);
            }
        }
        asm volatile("cp.async.commit_group;\n" ::: "memory");  // (possibly empty) group

        // scalars for next batch (latency hidden by wait+compute below)
        float2 ssa1 = ssa0, ssb1 = ssb0;
        if (has_next) {
            ssa1 = g_ss[ia1];
            ssb1 = g_ss[ib1];
        }

        // indices two batches ahead
        int ia2 = ia1, ib2 = ib1;
        if (has_next2) {
            int e2 = (bn + n_warps) * 4 + sub;
            int e2c = min(e2, n_edges - 1);
            ia2 = __ldg(ei + e2c);
            ib2 = __ldg(ei + n_edges + e2c);
        }

        // wait for CURRENT batch rows (1 newer group may stay in flight)
        if (has_next) {
            asm volatile("cp.async.wait_group 1;\n" ::: "memory");
        } else {
            asm volatile("cp.async.wait_group 0;\n" ::: "memory");
        }

        // compute current batch
        {
            unsigned char* ebuf = &sbuf[wib][stage][sub * 1024];
            const uint4* sA = (const uint4*)ebuf;
            const uint4* sB = (const uint4*)(ebuf + 512);

            int idot = 0;
#pragma unroll
            for (int j = 0; j < 4; j++) {
                uint4 a = sA[sl + 8 * j];
                uint4 bq = sB[sl + 8 * j];
                idot = __dp4a((int)a.x, (int)bq.x, idot);
                idot = __dp4a((int)a.y, (int)bq.y, idot);
                idot = __dp4a((int)a.z, (int)bq.z, idot);
                idot = __dp4a((int)a.w, (int)bq.w, idot);
            }

            unsigned gmask = 0xFFu << (sub * 8);
            idot = __reduce_add_sync(gmask, idot);

            int e = b * 4 + sub;
            if (sl == 0 && e < n_edges) {
                float dot = (float)idot * ssa0.x * ssb0.x;
                float d2 = 2.0f - 2.0f * dot
                         + 2.0f * EPS * (ssa0.y - ssb0.y)
                         + (float)D * EPS * EPS;
                d2 = fmaxf(d2, 0.0f);
                float v = 1.0f - sqrtf(d2);
                out[e] = 1.0f / (1.0f + expf(-v));
            }
        }

        // rotate pipeline state
        ia0 = ia1; ib0 = ib1; ssa0 = ssa1; ssb0 = ssb1;
        ia1 = ia2; ib1 = ib2;
        stage ^= 1;
    }
}

extern "C" void kernel_launch(void* const* d_in, const int* in_sizes, int n_in,
                              void* d_out, int out_size) {
    const float* z = (const float*)d_in[0];
    const int* ei  = (const int*)d_in[1];
    float* out     = (float*)d_out;

    int n_nodes = in_sizes[0] / D;   // 50000
    int n_edges = out_size;          // 150000

    {
        long long tt = (long long)n_nodes * 32;
        int blocks = (int)((tt + 255) / 256);
        normalize_kernel<<<blocks, 256>>>(z, n_nodes);
    }
    {
        int blocks = 148 * 3;   // persistent: 3 blocks/SM (64KB smem each)
        edge_kernel<<<blocks, 256>>>(ei, out, n_edges);
    }
}